// round 5
// baseline (speedup 1.0000x reference)
#include <cuda_runtime.h>
#include <cuda_fp16.h>
#include <math.h>

// Problem constants
#define B_  64
#define IC_ 2048
#define ID_ 16
#define K_  1024           // NC*CD = 64*16

// ---------------- device scratch (no allocations allowed) ------------------
__device__ __half g_uhat[(size_t)B_ * IC_ * K_]; // 256 MB  [b][i][k], fp16
__device__ float  g_s[3][B_ * K_];               // s per routing iteration (fp32)
__device__ float  g_v0[B_ * K_];
__device__ float  g_v1[B_ * K_];

// ---------------- f32x2 packed helpers (Blackwell) -------------------------
__device__ __forceinline__ unsigned long long pack2(float lo, float hi) {
    unsigned long long r;
    asm("mov.b64 %0, {%1, %2};" : "=l"(r) : "f"(lo), "f"(hi));
    return r;
}
__device__ __forceinline__ unsigned long long fma2(unsigned long long a,
                                                   unsigned long long b,
                                                   unsigned long long c) {
    unsigned long long d;
    asm("fma.rn.f32x2 %0, %1, %2, %3;" : "=l"(d) : "l"(a), "l"(b), "l"(c));
    return d;
}
__device__ __forceinline__ unsigned long long add2(unsigned long long a,
                                                   unsigned long long b) {
    unsigned long long d;
    asm("add.rn.f32x2 %0, %1, %2;" : "=l"(d) : "l"(a), "l"(b));
    return d;
}
__device__ __forceinline__ void unpack2(unsigned long long v, float& lo, float& hi) {
    asm("mov.b64 {%0, %1}, %2;" : "=f"(lo), "=f"(hi) : "l"(v));
}

// ---------------- kernel 0: s[0..2] <- bias broadcast ----------------------
__global__ __launch_bounds__(1024) void k_init(const float* __restrict__ bias) {
    const int blk = blockIdx.x;                    // 192 blocks: 3 bufs x 64 b
    g_s[blk >> 6][(blk & 63) * K_ + threadIdx.x] = bias[threadIdx.x];
}

// ---------------- kernel 1: projection + fused iter-0 mean -----------------
// grid = (2 kchunks, 2 bgroups, 64 isegs) = 256 CTAs, 256 threads.
// thread t owns k-pair (kbase+2t, kbase+2t+1) as one f32x2 lane.
// x is staged in smem PRE-DUPLICATED as (x,x) f32x2 pairs -> inner loop is
// pure broadcast LDS.128 + FFMA2, no per-FMA packing.
#define KC    512
#define BG    32
#define ISEG  32
__global__ __launch_bounds__(256, 2) void k_project(const float* __restrict__ x,
                                                    const float* __restrict__ W) {
    const int t     = threadIdx.x;
    const int kbase = blockIdx.x * KC;
    const int bbase = blockIdx.y * BG;
    const int i0    = blockIdx.z * ISEG;
    const int k2    = kbase + 2 * t;

    // packed (x,x) pairs: [b][ii][j] -> 32*16*16*8B = 64 KB (2 CTAs = 128 KB)
    extern __shared__ unsigned long long xsp[];
    #define XSP(b, ii, j) xsp[((b) * 16 + (ii)) * 16 + (j)]

    unsigned long long acc[BG];
    #pragma unroll
    for (int b = 0; b < BG; b++) acc[b] = 0ull;

    for (int half = 0; half < 2; half++) {
        __syncthreads();                           // protect previous xsp use
        // stage x[bbase..+32, i0+half*16 .. +16, :] duplicated into f32x2
        for (int r = t; r < 2048; r += 256) {      // 2048 float4 source reads
            const int b   = r >> 6;
            const int rem = r & 63;
            const int ii  = rem >> 2, q = rem & 3;
            const float4 v = *(const float4*)(x +
                ((size_t)(bbase + b) * IC_ + (i0 + half * 16 + ii)) * ID_ + q * 4);
            XSP(b, ii, q * 4 + 0) = pack2(v.x, v.x);
            XSP(b, ii, q * 4 + 1) = pack2(v.y, v.y);
            XSP(b, ii, q * 4 + 2) = pack2(v.z, v.z);
            XSP(b, ii, q * 4 + 3) = pack2(v.w, v.w);
        }
        __syncthreads();

        #pragma unroll 1
        for (int ii = 0; ii < 16; ii++) {
            const int i = i0 + half * 16 + ii;
            const float* Wi = W + (size_t)i * ID_ * K_ + k2;
            unsigned long long w[16];
            #pragma unroll
            for (int j = 0; j < 16; j++)
                w[j] = *(const unsigned long long*)(Wi + (size_t)j * K_);

            #pragma unroll 4
            for (int b = 0; b < BG; b++) {
                const ulonglong2* xv = (const ulonglong2*)&XSP(b, ii, 0);
                unsigned long long a = 0ull;
                #pragma unroll
                for (int jq = 0; jq < 8; jq++) {
                    const ulonglong2 p = xv[jq];   // broadcast LDS.128
                    a = fma2(w[2 * jq + 0], p.x, a);
                    a = fma2(w[2 * jq + 1], p.y, a);
                }
                float lo, hi;
                unpack2(a, lo, hi);
                *(__half2*)(g_uhat +
                    ((size_t)(bbase + b) * IC_ + i) * K_ + k2) =
                    __floats2half2_rn(lo, hi);
                acc[b] = add2(acc[b], a);          // fp32 mean accumulation
            }
        }
    }

    const float sc = 1.0f / 64.0f;                 // softmax(0) weight
    #pragma unroll 4
    for (int b = 0; b < BG; b++) {
        float lo, hi;
        unpack2(acc[b], lo, hi);
        float* sp = g_s[0] + (bbase + b) * K_ + k2;
        atomicAdd(sp,     lo * sc);
        atomicAdd(sp + 1, hi * sc);
    }
}

// ---------------- kernel 2: squash(s[it]) -> v0/v1/out ---------------------
__global__ __launch_bounds__(1024) void k_squash(int it, float* __restrict__ outbuf) {
    const int b = blockIdx.x, t = threadIdx.x;
    float sv = g_s[it][b * K_ + t];
    float sq = sv * sv;
    #pragma unroll
    for (int off = 8; off >= 1; off >>= 1)
        sq += __shfl_xor_sync(0xffffffffu, sq, off, 16);
    const float tt = sq + 1e-7f;
    const float norm = sqrtf(tt);
    const float f = tt / (1.0f + tt) / norm;
    float* dst = (it == 0) ? g_v0 : (it == 1 ? g_v1 : outbuf);
    dst[b * K_ + t] = f * sv;
}

// ---------------- kernel 3: routing pass, depth-2 pipelined ----------------
// grid = (16, 64 b), block = 128 (4 autonomous warps). Warp task = 32 i's.
// Lane owns capsules n0=lane, n1=lane+32. u rows stay packed (fp16) until
// consumed; loads for i+2 issue before processing i -> ~8 LDG.128/warp in
// flight -> DRAM-bound. SECOND pass logits: b2 = u.(v0+v1).
template <bool SECOND>
__global__ __launch_bounds__(128, 3) void k_route() {
    const int b    = blockIdx.y;
    const int wt   = blockIdx.x * 4 + (threadIdx.x >> 5);
    const int lane = threadIdx.x & 31;
    const int i0   = wt * 32;

    float vA[16], vB[16];
    {
        const float4* vp = (const float4*)(g_v0 + b * K_);
        #pragma unroll
        for (int q = 0; q < 4; q++) {
            float4 a = vp[lane * 4 + q];
            vA[4 * q] = a.x; vA[4 * q + 1] = a.y; vA[4 * q + 2] = a.z; vA[4 * q + 3] = a.w;
            float4 c = vp[(lane + 32) * 4 + q];
            vB[4 * q] = c.x; vB[4 * q + 1] = c.y; vB[4 * q + 2] = c.z; vB[4 * q + 3] = c.w;
        }
        if (SECOND) {
            const float4* vq = (const float4*)(g_v1 + b * K_);
            #pragma unroll
            for (int q = 0; q < 4; q++) {
                float4 a = vq[lane * 4 + q];
                vA[4 * q] += a.x; vA[4 * q + 1] += a.y; vA[4 * q + 2] += a.z; vA[4 * q + 3] += a.w;
                float4 c = vq[(lane + 32) * 4 + q];
                vB[4 * q] += c.x; vB[4 * q + 1] += c.y; vB[4 * q + 2] += c.z; vB[4 * q + 3] += c.w;
            }
        }
    }

    const uint4* base = (const uint4*)(g_uhat + ((size_t)b * IC_ + i0) * K_);
    const int ROWQ = K_ / 8;                       // uint4 per i-row

    float sA[16], sB[16];
    #pragma unroll
    for (int q = 0; q < 16; q++) { sA[q] = 0.f; sB[q] = 0.f; }

    // pipeline registers: cur = i, nxt = i+1, fetched each iter = i+2
    uint4 cA0, cA1, cB0, cB1, nA0, nA1, nB0, nB1;
    {
        const uint4* r0 = base;
        cA0 = r0[lane * 2]; cA1 = r0[lane * 2 + 1];
        cB0 = r0[64 + lane * 2]; cB1 = r0[64 + lane * 2 + 1];
        const uint4* r1 = base + ROWQ;
        nA0 = r1[lane * 2]; nA1 = r1[lane * 2 + 1];
        nB0 = r1[64 + lane * 2]; nB1 = r1[64 + lane * 2 + 1];
    }

    #pragma unroll 1
    for (int i = 0; i < 32; i++) {
        // issue loads for i+2 (clamped; last two iters re-load harmlessly)
        const int ip = (i + 2 < 32) ? (i + 2) : i;
        const uint4* rf = base + (size_t)ip * ROWQ;
        uint4 fA0 = rf[lane * 2], fA1 = rf[lane * 2 + 1];
        uint4 fB0 = rf[64 + lane * 2], fB1 = rf[64 + lane * 2 + 1];

        // convert current row to fp32
        float uA[16], uB[16];
        {
            const __half2* h;
            float2 f;
            h = (const __half2*)&cA0;
            #pragma unroll
            for (int w = 0; w < 4; w++) { f = __half22float2(h[w]); uA[2*w] = f.x; uA[2*w+1] = f.y; }
            h = (const __half2*)&cA1;
            #pragma unroll
            for (int w = 0; w < 4; w++) { f = __half22float2(h[w]); uA[8+2*w] = f.x; uA[8+2*w+1] = f.y; }
            h = (const __half2*)&cB0;
            #pragma unroll
            for (int w = 0; w < 4; w++) { f = __half22float2(h[w]); uB[2*w] = f.x; uB[2*w+1] = f.y; }
            h = (const __half2*)&cB1;
            #pragma unroll
            for (int w = 0; w < 4; w++) { f = __half22float2(h[w]); uB[8+2*w] = f.x; uB[8+2*w+1] = f.y; }
        }

        float a0 = 0.f, a1 = 0.f;
        #pragma unroll
        for (int q = 0; q < 16; q++) {
            a0 = fmaf(uA[q], vA[q], a0);
            a1 = fmaf(uB[q], vB[q], a1);
        }

        // softmax over 64 n without max-sub (|logit| bounded ~O(1))
        const float e0 = __expf(a0);
        const float e1 = __expf(a1);
        float z = e0 + e1;
        #pragma unroll
        for (int off = 16; off >= 1; off >>= 1)
            z += __shfl_xor_sync(0xffffffffu, z, off);
        const float rz = __fdividef(1.0f, z);
        const float c0 = e0 * rz, c1 = e1 * rz;

        #pragma unroll
        for (int q = 0; q < 16; q++) {
            sA[q] = fmaf(c0, uA[q], sA[q]);
            sB[q] = fmaf(c1, uB[q], sB[q]);
        }

        // rotate pipeline
        cA0 = nA0; cA1 = nA1; cB0 = nB0; cB1 = nB1;
        nA0 = fA0; nA1 = fA1; nB0 = fB0; nB1 = fB1;
    }

    float* sp = g_s[SECOND ? 2 : 1] + b * K_;
    #pragma unroll
    for (int q = 0; q < 16; q++) {
        atomicAdd(sp + lane * 16 + q, sA[q]);
        atomicAdd(sp + (lane + 32) * 16 + q, sB[q]);
    }
}

// ---------------- launcher -------------------------------------------------
extern "C" void kernel_launch(void* const* d_in, const int* in_sizes, int n_in,
                              void* d_out, int out_size) {
    const float* x    = (const float*)d_in[0];   // [64,2048,16]
    const float* W    = (const float*)d_in[1];   // [2048,16,1024]
    const float* bias = (const float*)d_in[2];   // [64,16] -> 1024
    float* out = (float*)d_out;                  // [64,64,16]

    const int xsp_bytes = BG * 16 * 16 * 8;      // 64 KB dynamic smem
    cudaFuncSetAttribute(k_project, cudaFuncAttributeMaxDynamicSharedMemorySize,
                         xsp_bytes);

    k_init<<<192, 1024>>>(bias);                         // s0,s1,s2 = bias
    k_project<<<dim3(2, 2, 64), 256, xsp_bytes>>>(x, W); // u_hat(fp16) + s0 mean
    k_squash<<<B_, 1024>>>(0, out);                      // v0

    k_route<false><<<dim3(16, B_), 128>>>();             // s1
    k_squash<<<B_, 1024>>>(1, out);                      // v1

    k_route<true><<<dim3(16, B_), 128>>>();              // s2
    k_squash<<<B_, 1024>>>(2, out);                      // v2 -> out
}